// round 5
// baseline (speedup 1.0000x reference)
#include <cuda_runtime.h>
#include <cuda_fp16.h>

// ---------------------------------------------------------------------------
// MLMM electrostatics.
// E(p) = KE * q_v * ( q_u*chi - chi^3*(r.mu) + chi^5 * sum(O * Q') )
// with Q' = Q - (trQ/3) I (traceless), Q'22 = -(Q'00+Q'11).
//
// Gather record per ML atom: 32 bytes, 32B-aligned (ONE L2 sector):
//   float4 {q, mux, muy, muz} | 8 x fp16 {Q'00,Q'01,Q'02,Q'10,Q'11,Q'12,Q'20,Q'21}
//
// This round: 2 pairs per thread (512-pair tiles) for doubled gather MLP --
// the profile showed no saturated pipe at 91% occupancy => latency exposure.
// dist/idx loads vectorized to float2/int2.
// ---------------------------------------------------------------------------

#define NML_MAX 50000
#define KE_CONST 14.399645351950548f
#define CUTOFF_A 10.0f
#define BLK 256
#define PPT 2
#define TILE (BLK * PPT)  // 512 pairs per block

// [2*u] : float4 {q, mu}; [2*u+1] : 8 fp16 Q' components
__device__ __align__(32) float4 g_packed[NML_MAX * 2];

__global__ void mlmm_prep_kernel(const float* __restrict__ q_ml,
                                 const float* __restrict__ mu,
                                 const float* __restrict__ Q,
                                 const float* __restrict__ e0,
                                 float* __restrict__ out,
                                 int nml) {
    int u = blockIdx.x * blockDim.x + threadIdx.x;
    if (u >= nml) return;

    out[u] = e0[u];

    float m0 = mu[3 * u + 0];
    float m1 = mu[3 * u + 1];
    float m2 = mu[3 * u + 2];

    float Qv[9];
#pragma unroll
    for (int k = 0; k < 9; k++) Qv[k] = Q[9 * u + k];
    float third_tr = (Qv[0] + Qv[4] + Qv[8]) * (1.0f / 3.0f);

    float t00 = Qv[0] - third_tr;
    float t11 = Qv[4] - third_tr;

    g_packed[2 * u + 0] = make_float4(q_ml[u], m0, m1, m2);

    __half2 h0 = __floats2half2_rn(t00,   Qv[1]);
    __half2 h1 = __floats2half2_rn(Qv[2], Qv[3]);
    __half2 h2 = __floats2half2_rn(t11,   Qv[5]);
    __half2 h3 = __floats2half2_rn(Qv[6], Qv[7]);

    uint4 packed;
    packed.x = *reinterpret_cast<unsigned int*>(&h0);
    packed.y = *reinterpret_cast<unsigned int*>(&h1);
    packed.z = *reinterpret_cast<unsigned int*>(&h2);
    packed.w = *reinterpret_cast<unsigned int*>(&h3);
    reinterpret_cast<uint4*>(g_packed)[2 * u + 1] = packed;
}

__device__ __forceinline__ float pair_energy(float d, int u,
                                             const float* __restrict__ sv,
                                             const float* __restrict__ so,
                                             float q_v) {
    // gathered ML-atom multipoles: one 32B sector, 2x LDG.128
    float4 p0 = g_packed[2 * u + 0];
    uint4  ph = reinterpret_cast<const uint4*>(g_packed)[2 * u + 1];

    float r0 = sv[0], r1 = sv[1], r2 = sv[2];
    float o00 = so[0], o01 = so[1], o02 = so[2];
    float o10 = so[3], o11 = so[4], o12 = so[5];
    float o20 = so[6], o21 = so[7], o22 = so[8];

    float chi  = __fdividef(1.0f, d);
    float chi2 = chi * chi;
    float chi3 = chi2 * chi;
    float chi5 = chi3 * chi2;

    float e = p0.x * chi;                                        // charge
    e -= chi3 * (r0 * p0.y + r1 * p0.z + r2 * p0.w);             // dipole

    float2 c0 = __half22float2(*reinterpret_cast<__half2*>(&ph.x));
    float2 c1 = __half22float2(*reinterpret_cast<__half2*>(&ph.y));
    float2 c2 = __half22float2(*reinterpret_cast<__half2*>(&ph.z));
    float2 c3 = __half22float2(*reinterpret_cast<__half2*>(&ph.w));

    float dot9 = c0.x * (o00 - o22)
               + c2.x * (o11 - o22)
               + c0.y * o01 + c1.x * o02 + c1.y * o10
               + c2.y * o12 + c3.x * o20 + c3.y * o21;
    e += chi5 * dot9;                                            // quadrupole

    return e * (KE_CONST * q_v);
}

__global__ void __launch_bounds__(BLK)
mlmm_pair_kernel(const float* __restrict__ dist,
                 const float* __restrict__ vec,
                 const float* __restrict__ outer,
                 const int* __restrict__ idx_u,
                 const int* __restrict__ idx_v,
                 const float* __restrict__ q_mm,
                 float* __restrict__ out,
                 int n) {
    __shared__ float s_vec[TILE * 3];
    __shared__ float s_out[TILE * 9];

    long long base = (long long)blockIdx.x * TILE;
    int cnt = n - (int)base;
    if (cnt > TILE) cnt = TILE;

    if (cnt == TILE) {
        const float4* v4 = (const float4*)(vec + 3 * base);
        float4*       sv = (float4*)s_vec;
#pragma unroll
        for (int t = threadIdx.x; t < TILE * 3 / 4; t += BLK) sv[t] = v4[t];

        const float4* o4 = (const float4*)(outer + 9 * base);
        float4*       so = (float4*)s_out;
#pragma unroll
        for (int t = threadIdx.x; t < TILE * 9 / 4; t += BLK) so[t] = o4[t];
    } else {
        for (int t = threadIdx.x; t < cnt * 3; t += BLK) s_vec[t] = vec[3 * base + t];
        for (int t = threadIdx.x; t < cnt * 9; t += BLK) s_out[t] = outer[9 * base + t];
    }
    __syncthreads();

    int lane2 = 2 * threadIdx.x;  // local index of first of this thread's 2 pairs

    if (lane2 + 1 < cnt) {
        long long i = base + lane2;

        // vectorized per-pair scalars (base even, 8B/8B aligned)
        float2 d2 = *reinterpret_cast<const float2*>(dist + i);
        int2   u2 = *reinterpret_cast<const int2*>(idx_u + i);
        int2   v2 = *reinterpret_cast<const int2*>(idx_v + i);

        bool m0 = (d2.x <= CUTOFF_A);
        bool m1 = (d2.y <= CUTOFF_A);

        // issue both q_v gathers up-front (independent chains)
        float qv0 = m0 ? __ldg(q_mm + u2.x * 0 + v2.x) : 0.0f;
        float qv1 = m1 ? __ldg(q_mm + v2.y) : 0.0f;

        if (m0) {
            float e = pair_energy(d2.x, u2.x, s_vec + 3 * lane2,
                                  s_out + 9 * lane2, qv0);
            atomicAdd(out + u2.x, e);
        }
        if (m1) {
            float e = pair_energy(d2.y, u2.y, s_vec + 3 * (lane2 + 1),
                                  s_out + 9 * (lane2 + 1), qv1);
            atomicAdd(out + u2.y, e);
        }
    } else {
        // tail: handle up to 2 pairs scalar
#pragma unroll
        for (int k = 0; k < PPT; k++) {
            int l = lane2 + k;
            if (l >= cnt) break;
            long long i = base + l;
            float d = dist[i];
            if (d > CUTOFF_A) continue;
            int u = idx_u[i];
            int v = idx_v[i];
            float e = pair_energy(d, u, s_vec + 3 * l, s_out + 9 * l,
                                  __ldg(q_mm + v));
            atomicAdd(out + u, e);
        }
    }
}

extern "C" void kernel_launch(void* const* d_in, const int* in_sizes, int n_in,
                              void* d_out, int out_size) {
    const float* q_ml  = (const float*)d_in[0];  // [NML]
    const float* q_mm  = (const float*)d_in[1];  // [NMM]
    const float* mu    = (const float*)d_in[2];  // [NML,3]
    const float* Q     = (const float*)d_in[3];  // [NML,3,3]
    const float* e0    = (const float*)d_in[4];  // [NML]
    const float* dist  = (const float*)d_in[5];  // [P]
    const float* vec   = (const float*)d_in[6];  // [P,3]
    const float* outer = (const float*)d_in[7];  // [P,3,3]
    const int*   idx_u = (const int*)d_in[8];    // [P] int32
    const int*   idx_v = (const int*)d_in[9];    // [P] int32

    float* out = (float*)d_out;

    int nml = in_sizes[0];
    int P   = in_sizes[5];

    {
        int threads = 256;
        int blocks  = (nml + threads - 1) / threads;
        mlmm_prep_kernel<<<blocks, threads>>>(q_ml, mu, Q, e0, out, nml);
    }
    {
        int blocks = (P + TILE - 1) / TILE;
        mlmm_pair_kernel<<<blocks, BLK>>>(dist, vec, outer, idx_u, idx_v,
                                          q_mm, out, P);
    }
}

// round 6
// speedup vs baseline: 1.5825x; 1.5825x over previous
#include <cuda_runtime.h>
#include <cuda_fp16.h>

// ---------------------------------------------------------------------------
// MLMM electrostatics.
// E(p) = KE * q_v * ( q_u*chi - chi^3*(r.mu) + chi^5 * sum(O * Q') )
// with Q' = Q - (trQ/3) I (traceless), Q'22 = -(Q'00+Q'11); identically
//   sum(O*Q) - (trO/3)*trQ == sum(O*Q').
//
// Gather record per ML atom: 32 bytes, 32B-aligned (ONE L2 sector):
//   float4 {q, mux, muy, muz} | 8 x fp16 {Q' components}
//
// R6: 1 pair/thread (R5's 2-pair version regressed). Software pipelining:
// the per-thread dist/idx/gather loads are issued BEFORE the smem staging
// loop + barrier, so ~470cyc of gather latency hides behind staging instead
// of extending the post-sync critical path.
// ---------------------------------------------------------------------------

#define NML_MAX 50000
#define KE_CONST 14.399645351950548f
#define CUTOFF_A 10.0f
#define BLK 256

// [2*u] : float4 {q, mu}; [2*u+1] : 8 fp16 Q' components
__device__ __align__(32) float4 g_packed[NML_MAX * 2];

__global__ void mlmm_prep_kernel(const float* __restrict__ q_ml,
                                 const float* __restrict__ mu,
                                 const float* __restrict__ Q,
                                 const float* __restrict__ e0,
                                 float* __restrict__ out,
                                 int nml) {
    int u = blockIdx.x * blockDim.x + threadIdx.x;
    if (u >= nml) return;

    out[u] = e0[u];

    float m0 = mu[3 * u + 0];
    float m1 = mu[3 * u + 1];
    float m2 = mu[3 * u + 2];

    float Qv[9];
#pragma unroll
    for (int k = 0; k < 9; k++) Qv[k] = Q[9 * u + k];
    float third_tr = (Qv[0] + Qv[4] + Qv[8]) * (1.0f / 3.0f);

    float t00 = Qv[0] - third_tr;
    float t11 = Qv[4] - third_tr;

    g_packed[2 * u + 0] = make_float4(q_ml[u], m0, m1, m2);

    __half2 h0 = __floats2half2_rn(t00,   Qv[1]);
    __half2 h1 = __floats2half2_rn(Qv[2], Qv[3]);
    __half2 h2 = __floats2half2_rn(t11,   Qv[5]);
    __half2 h3 = __floats2half2_rn(Qv[6], Qv[7]);

    uint4 packed;
    packed.x = *reinterpret_cast<unsigned int*>(&h0);
    packed.y = *reinterpret_cast<unsigned int*>(&h1);
    packed.z = *reinterpret_cast<unsigned int*>(&h2);
    packed.w = *reinterpret_cast<unsigned int*>(&h3);
    reinterpret_cast<uint4*>(g_packed)[2 * u + 1] = packed;
}

__global__ void __launch_bounds__(BLK)
mlmm_pair_kernel(const float* __restrict__ dist,
                 const float* __restrict__ vec,
                 const float* __restrict__ outer,
                 const int* __restrict__ idx_u,
                 const int* __restrict__ idx_v,
                 const float* __restrict__ q_mm,
                 float* __restrict__ out,
                 int n) {
    __shared__ float s_vec[BLK * 3];
    __shared__ float s_out[BLK * 9];

    long long base = (long long)blockIdx.x * BLK;
    int cnt = n - (int)base;
    if (cnt > BLK) cnt = BLK;

    int  lane   = threadIdx.x;
    bool inrange = (lane < cnt);
    long long i = base + lane;

    // ---- phase 1: issue per-thread loads EARLY (before staging + barrier) ----
    float d = 1e30f;
    if (inrange) d = dist[i];
    bool m = (d <= CUTOFF_A);

    int u = 0, v = 0;
    if (m) { u = idx_u[i]; v = idx_v[i]; }

    float4 p0 = make_float4(0.f, 0.f, 0.f, 0.f);
    uint4  ph = make_uint4(0u, 0u, 0u, 0u);
    float  qv = 0.f;
    if (m) {
        p0 = g_packed[2 * u + 0];
        ph = reinterpret_cast<const uint4*>(g_packed)[2 * u + 1];
        qv = __ldg(q_mm + v);
    }

    // ---- phase 2: stage vec/outer tiles (coalesced float4), overlap with
    //      the in-flight gathers ----
    if (cnt == BLK) {
        const float4* v4 = (const float4*)(vec + 3 * base);
        float4*       sv = (float4*)s_vec;
#pragma unroll
        for (int t = threadIdx.x; t < BLK * 3 / 4; t += BLK) sv[t] = v4[t];

        const float4* o4 = (const float4*)(outer + 9 * base);
        float4*       so = (float4*)s_out;
#pragma unroll
        for (int t = threadIdx.x; t < BLK * 9 / 4; t += BLK) so[t] = o4[t];
    } else {
        for (int t = threadIdx.x; t < cnt * 3; t += BLK) s_vec[t] = vec[3 * base + t];
        for (int t = threadIdx.x; t < cnt * 9; t += BLK) s_out[t] = outer[9 * base + t];
    }
    __syncthreads();

    if (!m) return;

    // ---- phase 3: math + scatter ----
    float r0 = s_vec[3 * lane + 0];
    float r1 = s_vec[3 * lane + 1];
    float r2 = s_vec[3 * lane + 2];

    const float* op = s_out + 9 * lane;
    float o00 = op[0], o01 = op[1], o02 = op[2];
    float o10 = op[3], o11 = op[4], o12 = op[5];
    float o20 = op[6], o21 = op[7], o22 = op[8];

    float chi  = __fdividef(1.0f, d);
    float chi2 = chi * chi;
    float chi3 = chi2 * chi;
    float chi5 = chi3 * chi2;

    // charge-charge
    float e = p0.x * chi;

    // dipole: - chi^3 * (r . mu)
    e -= chi3 * (r0 * p0.y + r1 * p0.z + r2 * p0.w);

    // quadrupole: + chi^5 * sum(O * Q'), Q'22 = -(Q'00 + Q'11)
    float2 c0 = __half22float2(*reinterpret_cast<__half2*>(&ph.x)); // t00, Q01
    float2 c1 = __half22float2(*reinterpret_cast<__half2*>(&ph.y)); // Q02, Q10
    float2 c2 = __half22float2(*reinterpret_cast<__half2*>(&ph.z)); // t11, Q12
    float2 c3 = __half22float2(*reinterpret_cast<__half2*>(&ph.w)); // Q20, Q21

    float dot9 = c0.x * (o00 - o22)
               + c2.x * (o11 - o22)
               + c0.y * o01 + c1.x * o02 + c1.y * o10
               + c2.y * o12 + c3.x * o20 + c3.y * o21;
    e += chi5 * dot9;

    e *= KE_CONST * qv;

    atomicAdd(out + u, e);
}

extern "C" void kernel_launch(void* const* d_in, const int* in_sizes, int n_in,
                              void* d_out, int out_size) {
    const float* q_ml  = (const float*)d_in[0];  // [NML]
    const float* q_mm  = (const float*)d_in[1];  // [NMM]
    const float* mu    = (const float*)d_in[2];  // [NML,3]
    const float* Q     = (const float*)d_in[3];  // [NML,3,3]
    const float* e0    = (const float*)d_in[4];  // [NML]
    const float* dist  = (const float*)d_in[5];  // [P]
    const float* vec   = (const float*)d_in[6];  // [P,3]
    const float* outer = (const float*)d_in[7];  // [P,3,3]
    const int*   idx_u = (const int*)d_in[8];    // [P] int32
    const int*   idx_v = (const int*)d_in[9];    // [P] int32

    float* out = (float*)d_out;

    int nml = in_sizes[0];
    int P   = in_sizes[5];

    {
        int threads = 256;
        int blocks  = (nml + threads - 1) / threads;
        mlmm_prep_kernel<<<blocks, threads>>>(q_ml, mu, Q, e0, out, nml);
    }
    {
        int blocks = (P + BLK - 1) / BLK;
        mlmm_pair_kernel<<<blocks, BLK>>>(dist, vec, outer, idx_u, idx_v,
                                          q_mm, out, P);
    }
}